// round 1
// baseline (speedup 1.0000x reference)
#include <cuda_runtime.h>
#include <cuda_bf16.h>
#include <math.h>
#include <stdint.h>

// Problem constants (fixed shapes for this problem instance)
#define N_ROWS   512
#define N_CAMS   8
#define M_PER    2048
#define D_FULL   4096
#define K_HALF   2048
#define P_TOT    16384      // N_CAMS * M_PER
#define TOPK     54         // covers top-51 (assoc) and top-33 (online) needs
#define INV_BETA 20.0f

// ---------------- scratch (device globals; no allocations allowed) ----------
__device__ float g_sims[2ull * N_ROWS * P_TOT];   // 64 MB: sims0, sims1
__device__ float g_loss[2 * N_ROWS * 3];          // per (half,row): ce, assoc, online

// ---------------- GEMM: C[h][n][p] = sum_k A[n][h*2048+k] * B[p][h*2048+k] ---
#define BM 64
#define BN 128
#define BK 16
#define TM 4
#define TN 8

__global__ __launch_bounds__(256, 3)
void gemm_kernel(const float* __restrict__ A,   // [512][4096] row-major
                 const float* __restrict__ B)   // [16384][4096] row-major
{
    const int h  = blockIdx.z;
    const int n0 = blockIdx.y * BM;
    const int p0 = blockIdx.x * BN;
    const int kbase = h * K_HALF;

    __shared__ float As[BK][BM + 4];
    __shared__ float Bs[BK][BN + 4];

    const int tid = threadIdx.x;
    const int a_row  = tid >> 2;          // 0..63
    const int a_col4 = (tid & 3) * 4;     // 0,4,8,12
    const int tx = tid & 15;              // p-dim
    const int ty = tid >> 4;              // n-dim

    const float* Aptr = A + (size_t)(n0 + a_row) * D_FULL + kbase + a_col4;
    const float* Bptr = B + (size_t)(p0 + a_row) * D_FULL + kbase + a_col4;

    float acc[TM][TN];
#pragma unroll
    for (int i = 0; i < TM; i++)
#pragma unroll
        for (int j = 0; j < TN; j++) acc[i][j] = 0.0f;

    for (int kt = 0; kt < K_HALF; kt += BK) {
        float4 av  = *(const float4*)(Aptr + kt);
        float4 bv0 = *(const float4*)(Bptr + kt);
        float4 bv1 = *(const float4*)(Bptr + kt + (size_t)64 * D_FULL);

        As[a_col4 + 0][a_row] = av.x;
        As[a_col4 + 1][a_row] = av.y;
        As[a_col4 + 2][a_row] = av.z;
        As[a_col4 + 3][a_row] = av.w;
        Bs[a_col4 + 0][a_row] = bv0.x;
        Bs[a_col4 + 1][a_row] = bv0.y;
        Bs[a_col4 + 2][a_row] = bv0.z;
        Bs[a_col4 + 3][a_row] = bv0.w;
        Bs[a_col4 + 0][a_row + 64] = bv1.x;
        Bs[a_col4 + 1][a_row + 64] = bv1.y;
        Bs[a_col4 + 2][a_row + 64] = bv1.z;
        Bs[a_col4 + 3][a_row + 64] = bv1.w;
        __syncthreads();

#pragma unroll
        for (int k = 0; k < BK; k++) {
            float4 a4  = *(const float4*)&As[k][ty * TM];
            float4 b4l = *(const float4*)&Bs[k][tx * TN];
            float4 b4h = *(const float4*)&Bs[k][tx * TN + 4];
            float ra[TM] = {a4.x, a4.y, a4.z, a4.w};
            float rb[TN] = {b4l.x, b4l.y, b4l.z, b4l.w, b4h.x, b4h.y, b4h.z, b4h.w};
#pragma unroll
            for (int i = 0; i < TM; i++)
#pragma unroll
                for (int j = 0; j < TN; j++)
                    acc[i][j] = fmaf(ra[i], rb[j], acc[i][j]);
        }
        __syncthreads();
    }

    float* Cbase = g_sims + ((size_t)h * N_ROWS + n0 + ty * TM) * P_TOT + p0 + tx * TN;
#pragma unroll
    for (int i = 0; i < TM; i++) {
        float4 v0 = make_float4(acc[i][0], acc[i][1], acc[i][2], acc[i][3]);
        float4 v1 = make_float4(acc[i][4], acc[i][5], acc[i][6], acc[i][7]);
        *(float4*)(Cbase + (size_t)i * P_TOT)     = v0;
        *(float4*)(Cbase + (size_t)i * P_TOT + 4) = v1;
    }
}

// ---------------- per-row loss reduction ------------------------------------
// One CTA per (row, half). Row (16384 floats) cached in dynamic smem.
__global__ void reduce_kernel(const int* __restrict__ cams,
                              const int* __restrict__ proxy)
{
    extern __shared__ float sh[];
    float* row  = sh;                        // 16384
    float* redv = sh + P_TOT;                // 256
    int*   redi = (int*)(redv + 256);        // 256

    __shared__ float camMax[N_CAMS];
    __shared__ int   camIdx[N_CAMS];
    __shared__ float topv[TOPK];
    __shared__ int   topi[TOPK];

    const int n = blockIdx.x;
    const int h = blockIdx.y;
    const int tid = threadIdx.x;

    const float* src = g_sims + ((size_t)h * N_ROWS + n) * P_TOT;
    for (int i = tid; i < P_TOT; i += 256) row[i] = src[i];
    __syncthreads();

    const int c = cams[n];
    const int p = proxy[n];
    const float rp = row[p];

    // ---- CE: logsumexp over cam block minus target logit ----
    float bm = -3.0e38f;
    for (int j = c * M_PER + tid; j < (c + 1) * M_PER; j += 256) bm = fmaxf(bm, row[j]);
    redv[tid] = bm; __syncthreads();
    for (int s = 128; s > 0; s >>= 1) {
        if (tid < s) redv[tid] = fmaxf(redv[tid], redv[tid + s]);
        __syncthreads();
    }
    bm = redv[0]; __syncthreads();
    float ssum = 0.0f;
    for (int j = c * M_PER + tid; j < (c + 1) * M_PER; j += 256)
        ssum += expf((row[j] - bm) * INV_BETA);
    redv[tid] = ssum; __syncthreads();
    for (int s = 128; s > 0; s >>= 1) {
        if (tid < s) redv[tid] += redv[tid + s];
        __syncthreads();
    }
    const float ce = bm * INV_BETA + logf(redv[0]) - rp * INV_BETA;
    __syncthreads();

    // ---- per-cam max/argmax (tie -> lower index, matching jnp.argmax) ----
    for (int cc = 0; cc < N_CAMS; cc++) {
        float bv = -3.0e38f; int bi = cc * M_PER;
        for (int j = cc * M_PER + tid; j < (cc + 1) * M_PER; j += 256)
            if (row[j] > bv) { bv = row[j]; bi = j; }
        redv[tid] = bv; redi[tid] = bi; __syncthreads();
        for (int s = 128; s > 0; s >>= 1) {
            if (tid < s) {
                float v2 = redv[tid + s]; int i2 = redi[tid + s];
                if (v2 > redv[tid] || (v2 == redv[tid] && i2 < redi[tid])) {
                    redv[tid] = v2; redi[tid] = i2;
                }
            }
            __syncthreads();
        }
        if (tid == 0) { camMax[cc] = redv[0]; camIdx[cc] = redi[0]; }
        __syncthreads();
    }

    // ---- top-54 (value,index) by destructive block argmax ----
    for (int it = 0; it < TOPK; it++) {
        float bv = -3.0e38f; int bi = 0;
        for (int j = tid; j < P_TOT; j += 256)
            if (row[j] > bv) { bv = row[j]; bi = j; }
        redv[tid] = bv; redi[tid] = bi; __syncthreads();
        for (int s = 128; s > 0; s >>= 1) {
            if (tid < s) {
                float v2 = redv[tid + s]; int i2 = redi[tid + s];
                if (v2 > redv[tid] || (v2 == redv[tid] && i2 < redi[tid])) {
                    redv[tid] = v2; redi[tid] = i2;
                }
            }
            __syncthreads();
        }
        if (tid == 0) { topv[it] = redv[0]; topi[it] = redi[0]; row[redi[0]] = -3.0e38f; }
        __syncthreads();
    }

    if (tid == 0) {
        // top-3 cams by camMax (tie -> lower index, matching lax.top_k)
        int o0 = 0;
        for (int cc = 1; cc < N_CAMS; cc++) if (camMax[cc] > camMax[o0]) o0 = cc;
        int o1 = -1;
        for (int cc = 0; cc < N_CAMS; cc++) {
            if (cc == o0) continue;
            if (o1 < 0 || camMax[cc] > camMax[o1]) o1 = cc;
        }
        int o2 = -1;
        for (int cc = 0; cc < N_CAMS; cc++) {
            if (cc == o0 || cc == o1) continue;
            if (o2 < 0 || camMax[cc] > camMax[o2]) o2 = cc;
        }
        const int ex0 = camIdx[o0], ex1 = camIdx[o1], ex2 = camIdx[o2];

        // ---- assoc: logsumexp over {pos} U top-50(excl proxy) minus pos ----
        const float pos = rp * INV_BETA;
        float vals[51]; int cnt = 0;
        vals[cnt++] = pos;
        for (int it = 0; it < TOPK && cnt < 51; it++) {
            if (topi[it] == p) continue;
            vals[cnt++] = topv[it] * INV_BETA;
        }
        float m1 = vals[0];
        for (int i = 1; i < 51; i++) m1 = fmaxf(m1, vals[i]);
        float s1 = 0.0f;
        for (int i = 0; i < 51; i++) s1 += expf(vals[i] - m1);
        const float assoc = m1 + logf(s1) - pos;

        // ---- online: lse over 3 cam-top logits + top-30 of rest, minus mean3
        const float l0 = camMax[o0] * INV_BETA;
        const float l1 = camMax[o1] * INV_BETA;
        const float l2 = camMax[o2] * INV_BETA;
        float ov[33]; int oc = 0;
        ov[oc++] = l0; ov[oc++] = l1; ov[oc++] = l2;
        for (int it = 0; it < TOPK && oc < 33; it++) {
            const int idx = topi[it];
            if (idx == ex0 || idx == ex1 || idx == ex2) continue;
            ov[oc++] = topv[it] * INV_BETA;
        }
        float m2 = ov[0];
        for (int i = 1; i < 33; i++) m2 = fmaxf(m2, ov[i]);
        float s2 = 0.0f;
        for (int i = 0; i < 33; i++) s2 += expf(ov[i] - m2);
        const float online = m2 + logf(s2) - (l0 + l1 + l2) * (1.0f / 3.0f);

        float* dst = g_loss + ((size_t)h * N_ROWS + n) * 3;
        dst[0] = ce; dst[1] = assoc; dst[2] = online;
    }
}

// ---------------- final deterministic weighted sum ---------------------------
__global__ void final_kernel(const int* __restrict__ cams, float* __restrict__ out)
{
    __shared__ double sd[N_ROWS];
    const int n = threadIdx.x;
    const int c = cams[n];
    int cnt = 0;
    for (int i = 0; i < N_ROWS; i++) cnt += (cams[i] == c);
    const double w = 1.0 / (double)cnt;
    const float* a = g_loss + (size_t)n * 3;               // half 0
    const float* b = g_loss + (size_t)(N_ROWS + n) * 3;    // half 1
    double t = 0.6 * ((double)a[0] + (double)b[0])
             + 0.7 * ((double)a[1] + (double)b[1])
             + 0.7 * ((double)a[2] + (double)b[2]);
    sd[n] = t * w;
    __syncthreads();
    for (int s = 256; s > 0; s >>= 1) {
        if (n < s) sd[n] += sd[n + s];
        __syncthreads();
    }
    if (n == 0) out[0] = (float)sd[0];
}

// ---------------- entry ------------------------------------------------------
extern "C" void kernel_launch(void* const* d_in, const int* in_sizes, int n_in,
                              void* d_out, int out_size)
{
    const float* features = (const float*)d_in[0];
    // d_in[1] = global_features (unused by the reference loss)
    const float* memory = (const float*)d_in[2];
    const int* cams  = (const int*)d_in[3];
    const int* proxy = (const int*)d_in[4];
    float* out = (float*)d_out;

    // GEMM: both halves
    dim3 ggrid(P_TOT / BN, N_ROWS / BM, 2);
    gemm_kernel<<<ggrid, 256>>>(features, memory);

    // Row reductions: 64KB row + reduction buffers in dynamic smem
    const int smem_bytes = (P_TOT + 256) * (int)sizeof(float) + 256 * (int)sizeof(int);
    cudaFuncSetAttribute(reduce_kernel, cudaFuncAttributeMaxDynamicSharedMemorySize,
                         smem_bytes);
    dim3 rgrid(N_ROWS, 2);
    reduce_kernel<<<rgrid, 256, smem_bytes>>>(cams, proxy);

    // Final scalar
    final_kernel<<<1, N_ROWS>>>(cams, out);
}

// round 3
// speedup vs baseline: 3.2733x; 3.2733x over previous
#include <cuda_runtime.h>
#include <cuda_bf16.h>
#include <math.h>
#include <stdint.h>

// Problem constants
#define N_ROWS   512
#define N_CAMS   8
#define M_PER    2048
#define D_FULL   4096
#define K_HALF   2048
#define P_TOT    16384
#define TOPK     54
#define INV_BETA 20.0f

// ---------------- scratch (device globals; no allocations allowed) ----------
__device__ float g_sims[2ull * N_ROWS * P_TOT];    // 64 MB
__device__ float g_loss[2 * N_ROWS * 3];
__device__ float g_featR[(size_t)N_ROWS * D_FULL]; // tf32-rounded features

// ---------------- helpers ----------------------------------------------------
__device__ __forceinline__ uint32_t smem_u32(const void* p) {
    uint32_t a;
    asm("{ .reg .u64 t; cvta.to.shared.u64 t, %1; cvt.u32.u64 %0, t; }"
        : "=r"(a) : "l"(p));
    return a;
}
__device__ __forceinline__ float tf32r(float f) {
    uint32_t r;
    asm("cvt.rna.tf32.f32 %0, %1;" : "=r"(r) : "f"(f));
    return __uint_as_float(r);
}
__device__ __forceinline__ uint32_t tf32u(float f) {
    uint32_t r;
    asm("cvt.rna.tf32.f32 %0, %1;" : "=r"(r) : "f"(f));
    return r;
}
__device__ __forceinline__ void cp16(uint32_t s, const void* g) {
    asm volatile("cp.async.cg.shared.global [%0], [%1], 16;" :: "r"(s), "l"(g));
}
#define CP_COMMIT() asm volatile("cp.async.commit_group;" ::: "memory")

__device__ __forceinline__ void mma8(float* d, const uint32_t* a,
                                     uint32_t b0, uint32_t b1) {
    asm volatile(
        "mma.sync.aligned.m16n8k8.row.col.f32.tf32.tf32.f32 "
        "{%0,%1,%2,%3}, {%4,%5,%6,%7}, {%8,%9}, {%0,%1,%2,%3};"
        : "+f"(d[0]), "+f"(d[1]), "+f"(d[2]), "+f"(d[3])
        : "r"(a[0]), "r"(a[1]), "r"(a[2]), "r"(a[3]), "r"(b0), "r"(b1));
}

// ---------------- tf32 pre-round of features ---------------------------------
__global__ void roundA_kernel(const float* __restrict__ f) {
    size_t i = (size_t)blockIdx.x * 256 + threadIdx.x;   // float4 index
    const float4 v = ((const float4*)f)[i];
    float4 o = make_float4(tf32r(v.x), tf32r(v.y), tf32r(v.z), tf32r(v.w));
    ((float4*)g_featR)[i] = o;
}

// ---------------- mma.sync tf32 GEMM ------------------------------------------
// CTA: 128x128 tile, 8 warps of 32x64. K chunk = 16, 3-stage cp.async ring.
// Smem per stage: A 128x20 floats (10240 B) + B 128x20 (10240 B) = 20480 B.
#define GBK      16
#define NSTG     (K_HALF / GBK)     // 128
#define STG_B    20480u
#define A_ROWB   80u                // 20 floats row stride

__device__ __forceinline__ void load_stage(int st, int tid, int mtile, int ntile,
                                           int h, uint32_t sbase,
                                           const float* __restrict__ Bmem) {
    const uint32_t buf = sbase + (uint32_t)(st % 3) * STG_B;
    const int kg = h * K_HALF + st * GBK;
#pragma unroll
    for (int i = 0; i < 2; i++) {
        int idx = tid + i * 256;         // 0..511
        int r = idx >> 2, ch = idx & 3;
        cp16(buf + (uint32_t)r * A_ROWB + (uint32_t)ch * 16,
             g_featR + (size_t)(mtile * 128 + r) * D_FULL + kg + ch * 4);
    }
#pragma unroll
    for (int i = 0; i < 2; i++) {
        int idx = tid + i * 256;
        int r = idx >> 2, ch = idx & 3;
        cp16(buf + 10240u + (uint32_t)r * A_ROWB + (uint32_t)ch * 16,
             Bmem + (size_t)(ntile * 128 + r) * D_FULL + kg + ch * 4);
    }
    CP_COMMIT();
}

__global__ void __launch_bounds__(256, 2)
gemm_mma(const float* __restrict__ Bmem) {
    extern __shared__ char sm[];
    const uint32_t sbase = smem_u32(sm);

    const int tid = threadIdx.x;
    const int bx = blockIdx.x;          // 0..511, mtile fastest for L2 B reuse
    const int h  = blockIdx.y;
    const int ntile = bx >> 2;
    const int mtile = bx & 3;

    const int w  = tid >> 5;
    const int l  = tid & 31;
    const int wm = (w & 3) * 32;        // warp M offset in tile
    const int wn = (w >> 2) * 64;       // warp N offset in tile
    const int g  = l >> 2;              // groupID
    const int tg = l & 3;               // thread-in-group

    float acc[2][8][4];
#pragma unroll
    for (int mi = 0; mi < 2; mi++)
#pragma unroll
        for (int ni = 0; ni < 8; ni++)
#pragma unroll
            for (int c = 0; c < 4; c++) acc[mi][ni][c] = 0.0f;

    load_stage(0, tid, mtile, ntile, h, sbase, Bmem);
    load_stage(1, tid, mtile, ntile, h, sbase, Bmem);
    load_stage(2, tid, mtile, ntile, h, sbase, Bmem);

    for (int st = 0; st < NSTG; st++) {
        if (st < NSTG - 2)      asm volatile("cp.async.wait_group 2;" ::: "memory");
        else if (st == NSTG - 2) asm volatile("cp.async.wait_group 1;" ::: "memory");
        else                    asm volatile("cp.async.wait_group 0;" ::: "memory");
        __syncthreads();

        const float* A = (const float*)(sm + (size_t)(st % 3) * STG_B);
        const float* B = A + 2560;      // 10240 bytes

#pragma unroll
        for (int ks = 0; ks < 2; ks++) {
            const int kb = ks * 8;
            uint32_t a[2][4];
#pragma unroll
            for (int mi = 0; mi < 2; mi++) {
                const float* ar = A + (wm + mi * 16 + g) * 20 + kb;
                a[mi][0] = __float_as_uint(ar[tg]);
                a[mi][2] = __float_as_uint(ar[tg + 4]);
                a[mi][1] = __float_as_uint(ar[160 + tg]);        // +8 rows
                a[mi][3] = __float_as_uint(ar[160 + tg + 4]);
            }
#pragma unroll
            for (int ni = 0; ni < 8; ni++) {
                const float* br = B + (wn + ni * 8 + g) * 20 + kb;
                uint32_t b0 = tf32u(br[tg]);
                uint32_t b1 = tf32u(br[tg + 4]);
                mma8(acc[0][ni], a[0], b0, b1);
                mma8(acc[1][ni], a[1], b0, b1);
            }
        }
        __syncthreads();
        if (st + 3 < NSTG) load_stage(st + 3, tid, mtile, ntile, h, sbase, Bmem);
    }

    // epilogue
    const int colbase = ntile * 128 + wn;
#pragma unroll
    for (int mi = 0; mi < 2; mi++) {
        const int row = mtile * 128 + wm + mi * 16 + g;
        float* d0 = g_sims + ((size_t)(h * N_ROWS + row)) * P_TOT + colbase + tg * 2;
        float* d1 = d0 + (size_t)8 * P_TOT;
#pragma unroll
        for (int ni = 0; ni < 8; ni++) {
            *(float2*)(d0 + ni * 8) = make_float2(acc[mi][ni][0], acc[mi][ni][1]);
            *(float2*)(d1 + ni * 8) = make_float2(acc[mi][ni][2], acc[mi][ni][3]);
        }
    }
}

// ---------------- per-row loss reduction (unchanged, known-good) -------------
__global__ void reduce_kernel(const int* __restrict__ cams,
                              const int* __restrict__ proxy)
{
    extern __shared__ float sh[];
    float* row  = sh;
    float* redv = sh + P_TOT;
    int*   redi = (int*)(redv + 256);

    __shared__ float camMax[N_CAMS];
    __shared__ int   camIdx[N_CAMS];
    __shared__ float topv[TOPK];
    __shared__ int   topi[TOPK];

    const int n = blockIdx.x;
    const int h = blockIdx.y;
    const int tid = threadIdx.x;

    const float* src = g_sims + ((size_t)h * N_ROWS + n) * P_TOT;
    for (int i = tid; i < P_TOT; i += 256) row[i] = src[i];
    __syncthreads();

    const int c = cams[n];
    const int p = proxy[n];
    const float rp = row[p];

    float bm = -3.0e38f;
    for (int j = c * M_PER + tid; j < (c + 1) * M_PER; j += 256) bm = fmaxf(bm, row[j]);
    redv[tid] = bm; __syncthreads();
    for (int s = 128; s > 0; s >>= 1) {
        if (tid < s) redv[tid] = fmaxf(redv[tid], redv[tid + s]);
        __syncthreads();
    }
    bm = redv[0]; __syncthreads();
    float ssum = 0.0f;
    for (int j = c * M_PER + tid; j < (c + 1) * M_PER; j += 256)
        ssum += expf((row[j] - bm) * INV_BETA);
    redv[tid] = ssum; __syncthreads();
    for (int s = 128; s > 0; s >>= 1) {
        if (tid < s) redv[tid] += redv[tid + s];
        __syncthreads();
    }
    const float ce = bm * INV_BETA + logf(redv[0]) - rp * INV_BETA;
    __syncthreads();

    for (int cc = 0; cc < N_CAMS; cc++) {
        float bv = -3.0e38f; int bi = cc * M_PER;
        for (int j = cc * M_PER + tid; j < (cc + 1) * M_PER; j += 256)
            if (row[j] > bv) { bv = row[j]; bi = j; }
        redv[tid] = bv; redi[tid] = bi; __syncthreads();
        for (int s = 128; s > 0; s >>= 1) {
            if (tid < s) {
                float v2 = redv[tid + s]; int i2 = redi[tid + s];
                if (v2 > redv[tid] || (v2 == redv[tid] && i2 < redi[tid])) {
                    redv[tid] = v2; redi[tid] = i2;
                }
            }
            __syncthreads();
        }
        if (tid == 0) { camMax[cc] = redv[0]; camIdx[cc] = redi[0]; }
        __syncthreads();
    }

    for (int it = 0; it < TOPK; it++) {
        float bv = -3.0e38f; int bi = 0;
        for (int j = tid; j < P_TOT; j += 256)
            if (row[j] > bv) { bv = row[j]; bi = j; }
        redv[tid] = bv; redi[tid] = bi; __syncthreads();
        for (int s = 128; s > 0; s >>= 1) {
            if (tid < s) {
                float v2 = redv[tid + s]; int i2 = redi[tid + s];
                if (v2 > redv[tid] || (v2 == redv[tid] && i2 < redi[tid])) {
                    redv[tid] = v2; redi[tid] = i2;
                }
            }
            __syncthreads();
        }
        if (tid == 0) { topv[it] = redv[0]; topi[it] = redi[0]; row[redi[0]] = -3.0e38f; }
        __syncthreads();
    }

    if (tid == 0) {
        int o0 = 0;
        for (int cc = 1; cc < N_CAMS; cc++) if (camMax[cc] > camMax[o0]) o0 = cc;
        int o1 = -1;
        for (int cc = 0; cc < N_CAMS; cc++) {
            if (cc == o0) continue;
            if (o1 < 0 || camMax[cc] > camMax[o1]) o1 = cc;
        }
        int o2 = -1;
        for (int cc = 0; cc < N_CAMS; cc++) {
            if (cc == o0 || cc == o1) continue;
            if (o2 < 0 || camMax[cc] > camMax[o2]) o2 = cc;
        }
        const int ex0 = camIdx[o0], ex1 = camIdx[o1], ex2 = camIdx[o2];

        const float pos = rp * INV_BETA;
        float vals[51]; int cnt = 0;
        vals[cnt++] = pos;
        for (int it = 0; it < TOPK && cnt < 51; it++) {
            if (topi[it] == p) continue;
            vals[cnt++] = topv[it] * INV_BETA;
        }
        float m1 = vals[0];
        for (int i = 1; i < 51; i++) m1 = fmaxf(m1, vals[i]);
        float s1 = 0.0f;
        for (int i = 0; i < 51; i++) s1 += expf(vals[i] - m1);
        const float assoc = m1 + logf(s1) - pos;

        const float l0 = camMax[o0] * INV_BETA;
        const float l1 = camMax[o1] * INV_BETA;
        const float l2 = camMax[o2] * INV_BETA;
        float ov[33]; int oc = 0;
        ov[oc++] = l0; ov[oc++] = l1; ov[oc++] = l2;
        for (int it = 0; it < TOPK && oc < 33; it++) {
            const int idx = topi[it];
            if (idx == ex0 || idx == ex1 || idx == ex2) continue;
            ov[oc++] = topv[it] * INV_BETA;
        }
        float m2 = ov[0];
        for (int i = 1; i < 33; i++) m2 = fmaxf(m2, ov[i]);
        float s2 = 0.0f;
        for (int i = 0; i < 33; i++) s2 += expf(ov[i] - m2);
        const float online = m2 + logf(s2) - (l0 + l1 + l2) * (1.0f / 3.0f);

        float* dst = g_loss + ((size_t)h * N_ROWS + n) * 3;
        dst[0] = ce; dst[1] = assoc; dst[2] = online;
    }
}

// ---------------- final deterministic weighted sum ---------------------------
__global__ void final_kernel(const int* __restrict__ cams, float* __restrict__ out)
{
    __shared__ double sd[N_ROWS];
    const int n = threadIdx.x;
    const int c = cams[n];
    int cnt = 0;
    for (int i = 0; i < N_ROWS; i++) cnt += (cams[i] == c);
    const double w = 1.0 / (double)cnt;
    const float* a = g_loss + (size_t)n * 3;
    const float* b = g_loss + (size_t)(N_ROWS + n) * 3;
    double t = 0.6 * ((double)a[0] + (double)b[0])
             + 0.7 * ((double)a[1] + (double)b[1])
             + 0.7 * ((double)a[2] + (double)b[2]);
    sd[n] = t * w;
    __syncthreads();
    for (int s = 256; s > 0; s >>= 1) {
        if (n < s) sd[n] += sd[n + s];
        __syncthreads();
    }
    if (n == 0) out[0] = (float)sd[0];
}

// ---------------- entry ------------------------------------------------------
extern "C" void kernel_launch(void* const* d_in, const int* in_sizes, int n_in,
                              void* d_out, int out_size)
{
    const float* features = (const float*)d_in[0];
    const float* memory = (const float*)d_in[2];
    const int* cams  = (const int*)d_in[3];
    const int* proxy = (const int*)d_in[4];
    float* out = (float*)d_out;

    // 1) tf32-round features
    roundA_kernel<<<2048, 256>>>(features);

    // 2) tensor-core GEMM (mma.sync tf32)
    const int gsmem = 3 * (int)STG_B;   // 61440
    cudaFuncSetAttribute(gemm_mma, cudaFuncAttributeMaxDynamicSharedMemorySize, gsmem);
    dim3 ggrid(512, 2);
    gemm_mma<<<ggrid, 256, gsmem>>>(memory);

    // 3) row reductions
    const int smem_bytes = (P_TOT + 256) * (int)sizeof(float) + 256 * (int)sizeof(int);
    cudaFuncSetAttribute(reduce_kernel, cudaFuncAttributeMaxDynamicSharedMemorySize,
                         smem_bytes);
    dim3 rgrid(N_ROWS, 2);
    reduce_kernel<<<rgrid, 256, smem_bytes>>>(cams, proxy);

    // 4) final scalar
    final_kernel<<<1, N_ROWS>>>(cams, out);
}

// round 4
// speedup vs baseline: 5.3235x; 1.6263x over previous
#include <cuda_runtime.h>
#include <cuda_bf16.h>
#include <math.h>
#include <stdint.h>

// Problem constants
#define N_ROWS   512
#define N_CAMS   8
#define M_PER    2048
#define D_FULL   4096
#define K_HALF   2048
#define P_TOT    16384
#define TOPK     54
#define INV_BETA 20.0f

// ---------------- scratch (device globals; no allocations allowed) ----------
__device__ float g_sims[2ull * N_ROWS * P_TOT];                 // 64 MB
__device__ float g_loss[2 * N_ROWS * 3];
__device__ __nv_bfloat16 g_featB[(size_t)N_ROWS * D_FULL];      // 4 MB
__device__ __nv_bfloat16 g_memB[(size_t)P_TOT * D_FULL];        // 128 MB

// ---------------- helpers ----------------------------------------------------
__device__ __forceinline__ uint32_t smem_u32(const void* p) {
    uint32_t a;
    asm("{ .reg .u64 t; cvta.to.shared.u64 t, %1; cvt.u32.u64 %0, t; }"
        : "=r"(a) : "l"(p));
    return a;
}
__device__ __forceinline__ void cp16(uint32_t s, const void* g) {
    asm volatile("cp.async.cg.shared.global [%0], [%1], 16;" :: "r"(s), "l"(g));
}
#define CP_COMMIT() asm volatile("cp.async.commit_group;" ::: "memory")

__device__ __forceinline__ void mma16(float* d, const uint32_t* a,
                                      uint32_t b0, uint32_t b1) {
    asm volatile(
        "mma.sync.aligned.m16n8k16.row.col.f32.bf16.bf16.f32 "
        "{%0,%1,%2,%3}, {%4,%5,%6,%7}, {%8,%9}, {%0,%1,%2,%3};"
        : "+f"(d[0]), "+f"(d[1]), "+f"(d[2]), "+f"(d[3])
        : "r"(a[0]), "r"(a[1]), "r"(a[2]), "r"(a[3]), "r"(b0), "r"(b1));
}

// ---------------- fp32 -> bf16 conversion ------------------------------------
__global__ void convA_k(const float* __restrict__ f) {
    size_t i = (size_t)blockIdx.x * 256 + threadIdx.x;   // float4 index
    float4 v = ((const float4*)f)[i];
    __nv_bfloat162 p0 = __floats2bfloat162_rn(v.x, v.y);
    __nv_bfloat162 p1 = __floats2bfloat162_rn(v.z, v.w);
    uint2 o;
    o.x = *(uint32_t*)&p0; o.y = *(uint32_t*)&p1;
    ((uint2*)g_featB)[i] = o;
}
__global__ void convB_k(const float* __restrict__ m) {
    size_t i = (size_t)blockIdx.x * 256 + threadIdx.x;
    float4 v = ((const float4*)m)[i];
    __nv_bfloat162 p0 = __floats2bfloat162_rn(v.x, v.y);
    __nv_bfloat162 p1 = __floats2bfloat162_rn(v.z, v.w);
    uint2 o;
    o.x = *(uint32_t*)&p0; o.y = *(uint32_t*)&p1;
    ((uint2*)g_memB)[i] = o;
}

// ---------------- bf16 mma.sync GEMM -------------------------------------------
// CTA: 128x128 tile, 8 warps (4M x 2N) of 32x64. K chunk = 32 bf16, 3-stage ring.
// Smem row stride 80 B (64 B data + 16 pad) -> conflict-free fragment loads.
#define GBK      32
#define NSTG     (K_HALF / GBK)     // 64
#define STG_B    20480u
#define ROWB     80u

__device__ __forceinline__ void load_stage(int st, int tid, int mtile, int ntile,
                                           int h, uint32_t sbase) {
    const uint32_t buf = sbase + (uint32_t)(st % 3) * STG_B;
    const int kg = h * K_HALF + st * GBK;
#pragma unroll
    for (int i = 0; i < 2; i++) {
        int idx = tid + i * 256;         // 0..511
        int r = idx >> 2, ch = idx & 3;  // 128 rows x 4 chunks(16B)
        cp16(buf + (uint32_t)r * ROWB + (uint32_t)ch * 16,
             g_featB + (size_t)(mtile * 128 + r) * D_FULL + kg + ch * 8);
    }
#pragma unroll
    for (int i = 0; i < 2; i++) {
        int idx = tid + i * 256;
        int r = idx >> 2, ch = idx & 3;
        cp16(buf + 10240u + (uint32_t)r * ROWB + (uint32_t)ch * 16,
             g_memB + (size_t)(ntile * 128 + r) * D_FULL + kg + ch * 8);
    }
    CP_COMMIT();
}

__global__ void __launch_bounds__(256, 2)
gemm_mma(void) {
    extern __shared__ char sm[];
    const uint32_t sbase = smem_u32(sm);

    const int tid = threadIdx.x;
    const int bx = blockIdx.x;          // mtile fastest -> 4 CTAs share B tile in L2
    const int h  = blockIdx.y;
    const int ntile = bx >> 2;
    const int mtile = bx & 3;

    const int w  = tid >> 5;
    const int l  = tid & 31;
    const int wm = (w & 3) * 32;
    const int wn = (w >> 2) * 64;
    const int g  = l >> 2;
    const int tg = l & 3;

    float acc[2][8][4];
#pragma unroll
    for (int mi = 0; mi < 2; mi++)
#pragma unroll
        for (int ni = 0; ni < 8; ni++)
#pragma unroll
            for (int c = 0; c < 4; c++) acc[mi][ni][c] = 0.0f;

    load_stage(0, tid, mtile, ntile, h, sbase);
    load_stage(1, tid, mtile, ntile, h, sbase);
    load_stage(2, tid, mtile, ntile, h, sbase);

    for (int st = 0; st < NSTG; st++) {
        if (st < NSTG - 2)       asm volatile("cp.async.wait_group 2;" ::: "memory");
        else if (st == NSTG - 2) asm volatile("cp.async.wait_group 1;" ::: "memory");
        else                     asm volatile("cp.async.wait_group 0;" ::: "memory");
        __syncthreads();

        const char* base = sm + (size_t)(st % 3) * STG_B;

#pragma unroll
        for (int ks = 0; ks < 2; ks++) {
            const int kb = ks * 32;           // bytes within 64B row
            uint32_t a[2][4];
#pragma unroll
            for (int mi = 0; mi < 2; mi++) {
                const char* ar = base + (wm + mi * 16 + g) * ROWB + kb + tg * 4;
                a[mi][0] = *(const uint32_t*)(ar);
                a[mi][1] = *(const uint32_t*)(ar + 8 * ROWB);
                a[mi][2] = *(const uint32_t*)(ar + 16);
                a[mi][3] = *(const uint32_t*)(ar + 8 * ROWB + 16);
            }
#pragma unroll
            for (int ni = 0; ni < 8; ni++) {
                const char* br = base + 10240 + (wn + ni * 8 + g) * ROWB + kb + tg * 4;
                uint32_t b0 = *(const uint32_t*)(br);
                uint32_t b1 = *(const uint32_t*)(br + 16);
                mma16(acc[0][ni], a[0], b0, b1);
                mma16(acc[1][ni], a[1], b0, b1);
            }
        }
        __syncthreads();
        if (st + 3 < NSTG) load_stage(st + 3, tid, mtile, ntile, h, sbase);
    }

    // epilogue
    const int colbase = ntile * 128 + wn;
#pragma unroll
    for (int mi = 0; mi < 2; mi++) {
        const int row = mtile * 128 + wm + mi * 16 + g;
        float* d0 = g_sims + ((size_t)(h * N_ROWS + row)) * P_TOT + colbase + tg * 2;
        float* d1 = d0 + (size_t)8 * P_TOT;
#pragma unroll
        for (int ni = 0; ni < 8; ni++) {
            *(float2*)(d0 + ni * 8) = make_float2(acc[mi][ni][0], acc[mi][ni][1]);
            *(float2*)(d1 + ni * 8) = make_float2(acc[mi][ni][2], acc[mi][ni][3]);
        }
    }
}

// ---------------- per-row loss reduction (radix-select top-k) ----------------
__device__ __forceinline__ uint32_t fkey(float v) {
    uint32_t u = __float_as_uint(v);
    return u ^ (uint32_t)(((int32_t)u >> 31) | 0x80000000);
}

__global__ void reduce_kernel(const int* __restrict__ cams,
                              const int* __restrict__ proxy)
{
    extern __shared__ float sh[];
    float* row = sh;                       // 16384 floats

    __shared__ float redv[256];
    __shared__ int   redi[256];
    __shared__ int   hist[256];
    __shared__ float candv[512];
    __shared__ int   candi[512];
    __shared__ float camMax[N_CAMS];
    __shared__ int   camIdx[N_CAMS];
    __shared__ float topv[TOPK];
    __shared__ int   topi[TOPK];
    __shared__ int   s_b1, s_above, s_count;
    __shared__ uint32_t s_thr;

    const int n = blockIdx.x;
    const int h = blockIdx.y;
    const int tid = threadIdx.x;

    const float* src = g_sims + ((size_t)h * N_ROWS + n) * P_TOT;
    for (int i = tid; i < P_TOT / 4; i += 256)
        ((float4*)row)[i] = ((const float4*)src)[i];
    __syncthreads();

    const int c = cams[n];
    const int p = proxy[n];
    const float rp = row[p];

    // ---- CE: logsumexp over cam block ----
    float bm = -3.0e38f;
    for (int j = c * M_PER + tid; j < (c + 1) * M_PER; j += 256) bm = fmaxf(bm, row[j]);
    redv[tid] = bm; __syncthreads();
    for (int s = 128; s > 0; s >>= 1) {
        if (tid < s) redv[tid] = fmaxf(redv[tid], redv[tid + s]);
        __syncthreads();
    }
    bm = redv[0]; __syncthreads();
    float ssum = 0.0f;
    for (int j = c * M_PER + tid; j < (c + 1) * M_PER; j += 256)
        ssum += expf((row[j] - bm) * INV_BETA);
    redv[tid] = ssum; __syncthreads();
    for (int s = 128; s > 0; s >>= 1) {
        if (tid < s) redv[tid] += redv[tid + s];
        __syncthreads();
    }
    const float ce = bm * INV_BETA + logf(redv[0]) - rp * INV_BETA;
    __syncthreads();

    // ---- per-cam max/argmax (tie -> lower index) ----
    for (int cc = 0; cc < N_CAMS; cc++) {
        float bv = -3.0e38f; int bi = cc * M_PER;
        for (int j = cc * M_PER + tid; j < (cc + 1) * M_PER; j += 256)
            if (row[j] > bv) { bv = row[j]; bi = j; }
        redv[tid] = bv; redi[tid] = bi; __syncthreads();
        for (int s = 128; s > 0; s >>= 1) {
            if (tid < s) {
                float v2 = redv[tid + s]; int i2 = redi[tid + s];
                if (v2 > redv[tid] || (v2 == redv[tid] && i2 < redi[tid])) {
                    redv[tid] = v2; redi[tid] = i2;
                }
            }
            __syncthreads();
        }
        if (tid == 0) { camMax[cc] = redv[0]; camIdx[cc] = redi[0]; }
        __syncthreads();
    }

    // ---- radix select: find 16-bit key threshold for top-54 ----
    hist[tid] = 0; __syncthreads();
    for (int j = tid; j < P_TOT; j += 256)
        atomicAdd(&hist[fkey(row[j]) >> 24], 1);
    __syncthreads();
    if (tid == 0) {
        int cum = 0, b = 255;
        for (; b >= 0; b--) { cum += hist[b]; if (cum >= TOPK) break; }
        s_b1 = b; s_above = cum - hist[b];
    }
    __syncthreads();
    const uint32_t b1 = (uint32_t)s_b1;
    hist[tid] = 0; __syncthreads();
    for (int j = tid; j < P_TOT; j += 256) {
        uint32_t k = fkey(row[j]);
        if ((k >> 24) == b1) atomicAdd(&hist[(k >> 16) & 0xFF], 1);
    }
    __syncthreads();
    if (tid == 0) {
        int cum = s_above, b = 255;
        for (; b >= 0; b--) { cum += hist[b]; if (cum >= TOPK) break; }
        s_thr = (b1 << 24) | ((uint32_t)b << 16);
        s_count = 0;
    }
    __syncthreads();
    const uint32_t thr = s_thr;
    for (int j = tid; j < P_TOT; j += 256) {
        if (fkey(row[j]) >= thr) {
            int k = atomicAdd(&s_count, 1);
            if (k < 512) { candv[k] = row[j]; candi[k] = j; }
        }
    }
    __syncthreads();

    // ---- exact top-54 (value desc, index asc) over candidates, warp 0 ----
    if (tid < 32) {
        const int nc = (s_count < 512) ? s_count : 512;
        for (int it = 0; it < TOPK; it++) {
            float bv = -3.0e38f; int bi = 0x7FFFFFFF;
            for (int k = tid; k < nc; k += 32) {
                float v = candv[k]; int ii = candi[k];
                if (v > bv || (v == bv && ii < bi)) { bv = v; bi = ii; }
            }
#pragma unroll
            for (int o = 16; o > 0; o >>= 1) {
                float ov = __shfl_down_sync(0xffffffff, bv, o);
                int   oi = __shfl_down_sync(0xffffffff, bi, o);
                if (ov > bv || (ov == bv && oi < bi)) { bv = ov; bi = oi; }
            }
            bv = __shfl_sync(0xffffffff, bv, 0);
            bi = __shfl_sync(0xffffffff, bi, 0);
            if (tid == 0) { topv[it] = bv; topi[it] = bi; }
            for (int k = tid; k < nc; k += 32)
                if (candi[k] == bi) candv[k] = -3.0e38f;
            __syncwarp();
        }
    }
    __syncthreads();

    if (tid == 0) {
        int o0 = 0;
        for (int cc = 1; cc < N_CAMS; cc++) if (camMax[cc] > camMax[o0]) o0 = cc;
        int o1 = -1;
        for (int cc = 0; cc < N_CAMS; cc++) {
            if (cc == o0) continue;
            if (o1 < 0 || camMax[cc] > camMax[o1]) o1 = cc;
        }
        int o2 = -1;
        for (int cc = 0; cc < N_CAMS; cc++) {
            if (cc == o0 || cc == o1) continue;
            if (o2 < 0 || camMax[cc] > camMax[o2]) o2 = cc;
        }
        const int ex0 = camIdx[o0], ex1 = camIdx[o1], ex2 = camIdx[o2];

        // assoc: lse over {pos} U top-50(excl proxy) minus pos
        const float pos = rp * INV_BETA;
        float vals[51]; int cnt = 0;
        vals[cnt++] = pos;
        for (int it = 0; it < TOPK && cnt < 51; it++) {
            if (topi[it] == p) continue;
            vals[cnt++] = topv[it] * INV_BETA;
        }
        float m1 = vals[0];
        for (int i = 1; i < 51; i++) m1 = fmaxf(m1, vals[i]);
        float s1 = 0.0f;
        for (int i = 0; i < 51; i++) s1 += expf(vals[i] - m1);
        const float assoc = m1 + logf(s1) - pos;

        // online: lse over 3 cam-top logits + top-30 of rest, minus mean3
        const float l0 = camMax[o0] * INV_BETA;
        const float l1 = camMax[o1] * INV_BETA;
        const float l2 = camMax[o2] * INV_BETA;
        float ov[33]; int oc = 0;
        ov[oc++] = l0; ov[oc++] = l1; ov[oc++] = l2;
        for (int it = 0; it < TOPK && oc < 33; it++) {
            const int idx = topi[it];
            if (idx == ex0 || idx == ex1 || idx == ex2) continue;
            ov[oc++] = topv[it] * INV_BETA;
        }
        float m2 = ov[0];
        for (int i = 1; i < 33; i++) m2 = fmaxf(m2, ov[i]);
        float s2 = 0.0f;
        for (int i = 0; i < 33; i++) s2 += expf(ov[i] - m2);
        const float online = m2 + logf(s2) - (l0 + l1 + l2) * (1.0f / 3.0f);

        float* dst = g_loss + ((size_t)h * N_ROWS + n) * 3;
        dst[0] = ce; dst[1] = assoc; dst[2] = online;
    }
}

// ---------------- final deterministic weighted sum ---------------------------
__global__ void final_kernel(const int* __restrict__ cams, float* __restrict__ out)
{
    __shared__ double sd[N_ROWS];
    __shared__ int scams[N_ROWS];
    const int n = threadIdx.x;
    scams[n] = cams[n];
    __syncthreads();
    const int c = scams[n];
    int cnt = 0;
    for (int i = 0; i < N_ROWS; i++) cnt += (scams[i] == c);
    const double w = 1.0 / (double)cnt;
    const float* a = g_loss + (size_t)n * 3;
    const float* b = g_loss + (size_t)(N_ROWS + n) * 3;
    double t = 0.6 * ((double)a[0] + (double)b[0])
             + 0.7 * ((double)a[1] + (double)b[1])
             + 0.7 * ((double)a[2] + (double)b[2]);
    sd[n] = t * w;
    __syncthreads();
    for (int s = 256; s > 0; s >>= 1) {
        if (n < s) sd[n] += sd[n + s];
        __syncthreads();
    }
    if (n == 0) out[0] = (float)sd[0];
}

// ---------------- entry ------------------------------------------------------
extern "C" void kernel_launch(void* const* d_in, const int* in_sizes, int n_in,
                              void* d_out, int out_size)
{
    const float* features = (const float*)d_in[0];
    const float* memory = (const float*)d_in[2];
    const int* cams  = (const int*)d_in[3];
    const int* proxy = (const int*)d_in[4];
    float* out = (float*)d_out;

    // 1) bf16 pre-conversion
    convA_k<<<(N_ROWS * D_FULL / 4) / 256, 256>>>(features);          // 2048 blocks
    convB_k<<<((size_t)P_TOT * D_FULL / 4) / 256, 256>>>(memory);     // 65536 blocks

    // 2) tensor-core GEMM (mma.sync bf16 m16n8k16)
    const int gsmem = 3 * (int)STG_B;   // 61440
    cudaFuncSetAttribute(gemm_mma, cudaFuncAttributeMaxDynamicSharedMemorySize, gsmem);
    dim3 ggrid(512, 2);
    gemm_mma<<<ggrid, 256, gsmem>>>();

    // 3) row reductions (radix-select)
    const int smem_bytes = P_TOT * (int)sizeof(float);
    cudaFuncSetAttribute(reduce_kernel, cudaFuncAttributeMaxDynamicSharedMemorySize,
                         smem_bytes);
    dim3 rgrid(N_ROWS, 2);
    reduce_kernel<<<rgrid, 256, smem_bytes>>>(cams, proxy);

    // 4) final scalar
    final_kernel<<<1, N_ROWS>>>(cams, out);
}